// round 9
// baseline (speedup 1.0000x reference)
#include <cuda_runtime.h>

// Row-linear streaming: 1024 CTAs, each owns 32 consecutive image rows
// (128 KB contiguous per input). Warp = 4 consecutive rows, fully sequential
// reads. Per-lane accumulators segmented by tile column (bx 0..7).
#define NUM_CTAS 1024
__device__ float g_partials[NUM_CTAS * 8];   // [cta][bx], signed 32-row-chunk sums
__device__ unsigned int g_done_count = 0;

__global__ void __launch_bounds__(256, 6) lthu_kernel(
    const float* __restrict__ fake, const float* __restrict__ real,
    float* __restrict__ out)
{
    __shared__ float s_part[8][8];    // [warp][bx]
    __shared__ float warp_sums[8];
    __shared__ bool is_last;

    const int lane = threadIdx.x & 31;
    const int wid  = threadIdx.x >> 5;

    // CTA -> (image, 32-row group); warp -> 4 consecutive rows
    const int img = blockIdx.x >> 5;          // 0..31
    const int rg  = blockIdx.x & 31;          // 0..31 (32 rows each)
    const int row0 = rg * 32 + wid * 4;

    const float4* f4 = (const float4*)(fake + (long)img * (1024 * 1024) + (long)row0 * 1024) + lane;
    const float4* r4 = (const float4*)(real + (long)img * (1024 * 1024) + (long)row0 * 1024) + lane;
    // row = 256 float4; segment bx = 32 float4 (one warp-wide load)

    float acc[8];
    #pragma unroll
    for (int s = 0; s < 8; ++s) acc[s] = 0.0f;

    #pragma unroll
    for (int r = 0; r < 4; ++r) {
        #pragma unroll
        for (int s = 0; s < 8; ++s) {
            float4 fv = f4[r * 256 + s * 32];
            float4 rv = r4[r * 256 + s * 32];
            acc[s] += (fv.x - rv.x) + (fv.y - rv.y) + (fv.z - rv.z) + (fv.w - rv.w);
        }
    }

    // warp-reduce each segment accumulator (no CTA barrier in hot path)
    #pragma unroll
    for (int s = 0; s < 8; ++s) {
        float v = acc[s];
        #pragma unroll
        for (int off = 16; off > 0; off >>= 1)
            v += __shfl_xor_sync(0xFFFFFFFFu, v, off);
        if (lane == 0) s_part[wid][s] = v;
    }

    __syncthreads();   // after all loads complete

    if (threadIdx.x == 0) {
        // combine 8 warps per segment; write 8 signed partials (thread 0 owns
        // all global writes so its __threadfence orders them)
        #pragma unroll
        for (int s = 0; s < 8; ++s) {
            float v = ((s_part[0][s] + s_part[1][s]) + (s_part[2][s] + s_part[3][s]))
                    + ((s_part[4][s] + s_part[5][s]) + (s_part[6][s] + s_part[7][s]));
            g_partials[blockIdx.x * 8 + s] = v;
        }
        __threadfence();
        unsigned int prev = atomicAdd(&g_done_count, 1u);
        is_last = (prev == NUM_CTAS - 1);
    }
    __syncthreads();

    if (is_last) {
        // 2048 tiles, 8 per thread, fixed order: sum 4 row-chunks -> abs -> sum
        float s = 0.0f;
        #pragma unroll
        for (int it = 0; it < 8; ++it) {
            int t   = threadIdx.x + it * 256;   // tile 0..2047
            int ti  = t >> 6;                   // image
            int rem = t & 63;
            int by  = rem >> 3;
            int bx  = rem & 7;
            int base = ((ti * 32) + (by * 4)) * 8 + bx;  // sub-chunk 0
            float v = (g_partials[base] + g_partials[base + 8])
                    + (g_partials[base + 16] + g_partials[base + 24]);
            s += fabsf(v);
        }

        #pragma unroll
        for (int off = 16; off > 0; off >>= 1)
            s += __shfl_xor_sync(0xFFFFFFFFu, s, off);
        if (lane == 0) warp_sums[wid] = s;
        __syncthreads();
        if (wid == 0) {
            float v = (lane < 8) ? warp_sums[lane] : 0.0f;
            #pragma unroll
            for (int off = 4; off > 0; off >>= 1)
                v += __shfl_xor_sync(0xFFFFFFFFu, v, off);
            if (lane == 0) {
                out[0] = v * (1.0f / (16384.0f * 32.0f));
                g_done_count = 0;   // reset for next graph replay
            }
        }
    }
}

extern "C" void kernel_launch(void* const* d_in, const int* in_sizes, int n_in,
                              void* d_out, int out_size)
{
    const float* fake = (const float*)d_in[0];
    const float* real = (const float*)d_in[1];
    float* out = (float*)d_out;

    lthu_kernel<<<NUM_CTAS, 256>>>(fake, real, out);
}

// round 10
// speedup vs baseline: 1.1394x; 1.1394x over previous
#include <cuda_runtime.h>

// 32 images * 64 tiles = 2048 tiles; each tile = 4 row-slices (32 rows x 128 cols)
// 8192 slices, one per warp. 1024 CTAs x 8 warps; each CTA owns 2 whole tiles.
#define NUM_TILES  2048
#define NUM_CTAS   1024
__device__ float g_cta_sums[NUM_CTAS];   // per-CTA: |tile0 sum| + |tile1 sum|
__device__ unsigned int g_done_count = 0;

// L1-bypass float4 load (ld.global.cg.v4): zero reuse -> skip L1 allocation.
__device__ __forceinline__ float4 ldcg4(const float4* p)
{
    float4 v;
    asm volatile("ld.global.cg.v4.f32 {%0,%1,%2,%3}, [%4];"
                 : "=f"(v.x), "=f"(v.y), "=f"(v.z), "=f"(v.w)
                 : "l"(p));
    return v;
}

__global__ void __launch_bounds__(256, 7) lthu_kernel(
    const float* __restrict__ fake, const float* __restrict__ real,
    float* __restrict__ out)
{
    __shared__ float slice_sums[8];   // one per warp
    __shared__ float warp_sums[8];
    __shared__ bool is_last;

    const int lane  = threadIdx.x & 31;
    const int wid   = threadIdx.x >> 5;
    const int slice = blockIdx.x * 8 + wid;   // 0..8191

    const int tile = slice >> 2;              // 0..2047
    const int q    = slice & 3;               // row group q*32 .. q*32+31
    const int b    = tile >> 6;               // image (64 tiles per image)
    const int rem  = tile & 63;
    const int by   = rem >> 3;
    const int bx   = rem & 7;
    const long base = (long)b * (1024 * 1024)
                    + (long)(by * 128 + q * 32) * 1024
                    + (long)bx * 128;

    const float4* f4 = (const float4*)(fake + base) + lane;
    const float4* r4 = (const float4*)(real + base) + lane;
    // slice: 32 rows x 32 float4/row; row stride in float4 units = 256

    float acc = 0.0f;
    #pragma unroll 16
    for (int r = 0; r < 32; ++r) {
        float4 fv = ldcg4(f4 + r * 256);
        float4 rv = ldcg4(r4 + r * 256);
        acc += (fv.x - rv.x) + (fv.y - rv.y) + (fv.z - rv.z) + (fv.w - rv.w);
    }

    // warp-local reduce — no CTA barrier while other warps stream
    #pragma unroll
    for (int off = 16; off > 0; off >>= 1)
        acc += __shfl_xor_sync(0xFFFFFFFFu, acc, off);

    if (lane == 0)
        slice_sums[wid] = acc;     // signed slice sum, in shared

    __syncthreads();               // after all loads complete

    if (threadIdx.x == 0) {
        // CTA owns two complete tiles: slices 0-3 and 4-7
        float t0 = (slice_sums[0] + slice_sums[1]) + (slice_sums[2] + slice_sums[3]);
        float t1 = (slice_sums[4] + slice_sums[5]) + (slice_sums[6] + slice_sums[7]);
        g_cta_sums[blockIdx.x] = fabsf(t0) + fabsf(t1);
        __threadfence();
        unsigned int prev = atomicAdd(&g_done_count, 1u);
        is_last = (prev == NUM_CTAS - 1);
    }
    __syncthreads();

    if (is_last) {
        // fixed-order deterministic reduce of 1024 per-CTA sums
        float s = 0.0f;
        #pragma unroll
        for (int it = 0; it < 4; ++it)
            s += g_cta_sums[threadIdx.x + it * 256];

        #pragma unroll
        for (int off = 16; off > 0; off >>= 1)
            s += __shfl_xor_sync(0xFFFFFFFFu, s, off);
        if (lane == 0) warp_sums[wid] = s;
        __syncthreads();
        if (wid == 0) {
            float v = (lane < 8) ? warp_sums[lane] : 0.0f;
            #pragma unroll
            for (int off = 4; off > 0; off >>= 1)
                v += __shfl_xor_sync(0xFFFFFFFFu, v, off);
            if (lane == 0) {
                out[0] = v * (1.0f / (16384.0f * 32.0f));
                g_done_count = 0;   // reset for next graph replay
            }
        }
    }
}

extern "C" void kernel_launch(void* const* d_in, const int* in_sizes, int n_in,
                              void* d_out, int out_size)
{
    const float* fake = (const float*)d_in[0];
    const float* real = (const float*)d_in[1];
    float* out = (float*)d_out;

    lthu_kernel<<<NUM_CTAS, 256>>>(fake, real, out);
}

// round 11
// speedup vs baseline: 1.1451x; 1.0050x over previous
#include <cuda_runtime.h>

// FINAL (R8): HBM-roofed streaming reduction.
// 32 images * 64 tiles = 2048 tiles; each tile = 4 row-slices (32 rows x 128 cols)
// 8192 slices, one per warp. 1024 CTAs x 8 warps; each CTA owns 2 whole tiles.
// Measured 6.25 TB/s — at the chip's load-path cap (all structural variants
// pin 6.20-6.26 TB/s across occ 48-89%, MLP 2-8, cache policies, patterns).
#define NUM_TILES  2048
#define NUM_CTAS   1024
__device__ float g_cta_sums[NUM_CTAS];   // per-CTA: |tile0 sum| + |tile1 sum|
__device__ unsigned int g_done_count = 0;

__global__ void __launch_bounds__(256, 7) lthu_kernel(
    const float* __restrict__ fake, const float* __restrict__ real,
    float* __restrict__ out)
{
    __shared__ float slice_sums[8];   // one per warp
    __shared__ float warp_sums[8];
    __shared__ bool is_last;

    const int lane  = threadIdx.x & 31;
    const int wid   = threadIdx.x >> 5;
    const int slice = blockIdx.x * 8 + wid;   // 0..8191

    const int tile = slice >> 2;              // 0..2047 (wid 0-3 -> tile 2*blk, 4-7 -> 2*blk+1)
    const int q    = slice & 3;               // row group q*32 .. q*32+31
    const int b    = tile >> 6;               // image (64 tiles per image)
    const int rem  = tile & 63;
    const int by   = rem >> 3;
    const int bx   = rem & 7;
    const long base = (long)b * (1024 * 1024)
                    + (long)(by * 128 + q * 32) * 1024
                    + (long)bx * 128;

    const float4* f4 = (const float4*)(fake + base) + lane;
    const float4* r4 = (const float4*)(real + base) + lane;
    // slice: 32 rows x 32 float4/row; row stride in float4 units = 256

    float acc = 0.0f;
    #pragma unroll 16
    for (int r = 0; r < 32; ++r) {
        float4 fv = f4[r * 256];
        float4 rv = r4[r * 256];
        acc += (fv.x - rv.x) + (fv.y - rv.y) + (fv.z - rv.z) + (fv.w - rv.w);
    }

    // warp-local reduce — no CTA barrier while other warps stream
    #pragma unroll
    for (int off = 16; off > 0; off >>= 1)
        acc += __shfl_xor_sync(0xFFFFFFFFu, acc, off);

    if (lane == 0)
        slice_sums[wid] = acc;     // signed slice sum, in shared

    __syncthreads();               // single barrier, after all loads complete

    if (threadIdx.x == 0) {
        // CTA owns two complete tiles: slices 0-3 and 4-7
        float t0 = (slice_sums[0] + slice_sums[1]) + (slice_sums[2] + slice_sums[3]);
        float t1 = (slice_sums[4] + slice_sums[5]) + (slice_sums[6] + slice_sums[7]);
        g_cta_sums[blockIdx.x] = fabsf(t0) + fabsf(t1);
        __threadfence();
        unsigned int prev = atomicAdd(&g_done_count, 1u);
        is_last = (prev == NUM_CTAS - 1);
    }
    __syncthreads();

    if (is_last) {
        // fixed-order deterministic reduce of 1024 per-CTA sums
        float s = 0.0f;
        #pragma unroll
        for (int it = 0; it < 4; ++it)
            s += g_cta_sums[threadIdx.x + it * 256];

        #pragma unroll
        for (int off = 16; off > 0; off >>= 1)
            s += __shfl_xor_sync(0xFFFFFFFFu, s, off);
        if (lane == 0) warp_sums[wid] = s;
        __syncthreads();
        if (wid == 0) {
            float v = (lane < 8) ? warp_sums[lane] : 0.0f;
            #pragma unroll
            for (int off = 4; off > 0; off >>= 1)
                v += __shfl_xor_sync(0xFFFFFFFFu, v, off);
            if (lane == 0) {
                out[0] = v * (1.0f / (16384.0f * 32.0f));
                g_done_count = 0;   // reset for next graph replay
            }
        }
    }
}

extern "C" void kernel_launch(void* const* d_in, const int* in_sizes, int n_in,
                              void* d_out, int out_size)
{
    const float* fake = (const float*)d_in[0];
    const float* real = (const float*)d_in[1];
    float* out = (float*)d_out;

    lthu_kernel<<<NUM_CTAS, 256>>>(fake, real, out);
}